// round 4
// baseline (speedup 1.0000x reference)
#include <cuda_runtime.h>
#include <cuda_bf16.h>
#include <math.h>

// ---------------------------------------------------------------------------
// Problem constants (match reference)
// ---------------------------------------------------------------------------
#define NB      512     // BATCH
#define NA      256     // N_ASSETS
#define CMAX    0.05f   // MAX_WEIGHT
#define NITERS  300     // FISTA iterations
#define NPOW    30      // power iterations
#define NEWTMAX 30      // max safeguarded Newton iterations (typ. exits in ~3)

// Scratch: symmetric-compressed Q per batch (compact in GMEM, padded in SMEM).
__device__ float dRf[(size_t)NB * 128 * 256];   // rows 0..127 of Q, full width
__device__ float dDf[(size_t)NB * 128 * 128];   // Q[128+i][128+j]

// ---------------------------------------------------------------------------
// Kernel 1: Q = A^T A  (tiles (0,0),(0,1),(1,1) only; Q symmetric)
// ---------------------------------------------------------------------------
__global__ __launch_bounds__(256) void qgemm_kernel(const float* __restrict__ A) {
    const int tile = blockIdx.x;               // 0:(0,0) 1:(0,128) 2:(128,128)
    const int b    = blockIdx.y;
    const int cj   = (tile == 2) ? 128 : 0;    // row window of Q
    const int ck   = (tile == 0) ? 0   : 128;  // col window of Q

    __shared__ float sA[16][128];
    __shared__ float sB[16][128];

    const int tid = threadIdx.x;
    const int tx  = tid & 15;
    const int ty  = tid >> 4;

    float acc[8][8];
#pragma unroll
    for (int i = 0; i < 8; ++i)
#pragma unroll
        for (int j = 0; j < 8; ++j) acc[i][j] = 0.f;

    const float* __restrict__ Ab = A + (size_t)b * NA * NA;

    for (int ic = 0; ic < NA; ic += 16) {
#pragma unroll
        for (int u = 0; u < 2; ++u) {
            int idx = tid * 8 + u * 4;
            int r   = idx >> 7;
            int cc  = idx & 127;
            *(float4*)&sA[r][cc] = *(const float4*)&Ab[(size_t)(ic + r) * NA + cj + cc];
            *(float4*)&sB[r][cc] = *(const float4*)&Ab[(size_t)(ic + r) * NA + ck + cc];
        }
        __syncthreads();

#pragma unroll
        for (int kk = 0; kk < 16; ++kk) {
            float a8[8], b8[8];
            const float4* pa = (const float4*)&sA[kk][ty * 8];
            const float4* pb = (const float4*)&sB[kk][tx * 8];
            float4 a0 = pa[0], a1 = pa[1];
            float4 b0 = pb[0], b1 = pb[1];
            a8[0]=a0.x; a8[1]=a0.y; a8[2]=a0.z; a8[3]=a0.w;
            a8[4]=a1.x; a8[5]=a1.y; a8[6]=a1.z; a8[7]=a1.w;
            b8[0]=b0.x; b8[1]=b0.y; b8[2]=b0.z; b8[3]=b0.w;
            b8[4]=b1.x; b8[5]=b1.y; b8[6]=b1.z; b8[7]=b1.w;
#pragma unroll
            for (int i = 0; i < 8; ++i)
#pragma unroll
                for (int j = 0; j < 8; ++j)
                    acc[i][j] = fmaf(a8[i], b8[j], acc[i][j]);
        }
        __syncthreads();
    }

#pragma unroll
    for (int i = 0; i < 8; ++i) {
        int row = ty * 8 + i;
        float4 v0 = make_float4(acc[i][0], acc[i][1], acc[i][2], acc[i][3]);
        float4 v1 = make_float4(acc[i][4], acc[i][5], acc[i][6], acc[i][7]);
        if (tile < 2) {
            float* dst = dRf + ((size_t)b * 128 + row) * 256 + ck + tx * 8;
            *(float4*)dst       = v0;
            *(float4*)(dst + 4) = v1;
        } else {
            float* dst = dDf + ((size_t)b * 128 + row) * 128 + tx * 8;
            *(float4*)dst       = v0;
            *(float4*)(dst + 4) = v1;
        }
    }
}

// ---------------------------------------------------------------------------
// Kernel 2: per-batch FISTA, Q resident in SMEM, warp-replicated projection
// with early-exit safeguarded Newton (warm-started across FISTA iterations).
// ---------------------------------------------------------------------------
#define RP 260
#define DP 132
#define SR_ELEMS (128 * RP)
#define SD_ELEMS (128 * DP)
#define SMEM_FLOATS (SR_ELEMS + SD_ELEMS + 256 + 256 + 64)
#define SMEM_BYTES (SMEM_FLOATS * 4)

// block reduction (power-iteration phase only)
__device__ __forceinline__ float blk_sum(float a, float* red, int t) {
#pragma unroll
    for (int o = 16; o > 0; o >>= 1)
        a += __shfl_xor_sync(0xffffffffu, a, o);
    if ((t & 31) == 0) red[t >> 5] = a;
    __syncthreads();
    float r = 0.f;
#pragma unroll
    for (int i = 0; i < 8; ++i) r += red[i];
    __syncthreads();
    return r;
}

// g_t = sum_k Q[k][t] * y[k]  (symmetric-compressed, 4 independent accums)
__device__ __forceinline__ float matvec256(const float* __restrict__ sR,
                                           const float* __restrict__ sD,
                                           const float* __restrict__ sy,
                                           int t) {
    float g0 = 0.f, g1 = 0.f, g2 = 0.f, g3 = 0.f;
    const float4* __restrict__ y4 = (const float4*)sy;
    if (t < 128) {
        const float4* __restrict__ qr = (const float4*)(sR + t * RP);
#pragma unroll
        for (int k = 0; k < 64; ++k) {
            float4 q = y4 ? qr[k] : qr[k];
            float4 y = y4[k];
            g0 = fmaf(q.x, y.x, g0); g1 = fmaf(q.y, y.y, g1);
            g2 = fmaf(q.z, y.z, g2); g3 = fmaf(q.w, y.w, g3);
        }
    } else {
        const float* __restrict__ qc = sR + t;
#pragma unroll
        for (int k4 = 0; k4 < 32; ++k4) {
            float4 y = y4[k4];
            const int k = k4 * 4;
            g0 = fmaf(qc[(k + 0) * RP], y.x, g0);
            g1 = fmaf(qc[(k + 1) * RP], y.y, g1);
            g2 = fmaf(qc[(k + 2) * RP], y.z, g2);
            g3 = fmaf(qc[(k + 3) * RP], y.w, g3);
        }
        const float4* __restrict__ dr = (const float4*)(sD + (t - 128) * DP);
#pragma unroll
        for (int k = 0; k < 32; ++k) {
            float4 q = dr[k], y = y4[k + 32];
            g0 = fmaf(q.x, y.x, g0); g1 = fmaf(q.y, y.y, g1);
            g2 = fmaf(q.z, y.z, g2); g3 = fmaf(q.w, y.w, g3);
        }
    }
    return (g0 + g1) + (g2 + g3);
}

__global__ __launch_bounds__(256) void fista_kernel(float* __restrict__ out) {
    extern __shared__ float sm[];
    float* sR  = sm;
    float* sD  = sm + SR_ELEMS;
    float* sy  = sD + SD_ELEMS;
    float* sv  = sy + 256;
    float* red = sv + 256;

    const int b    = blockIdx.x;
    const int t    = threadIdx.x;
    const int lane = t & 31;
    const int wid  = t >> 5;

    // --- load compressed Q into padded SMEM (float4 granularity) ---
    {
        const float4* __restrict__ gR = (const float4*)(dRf + (size_t)b * 128 * 256);
        float4* sR4 = (float4*)sR;
        for (int i = t; i < 128 * 64; i += 256) {
            int r = i >> 6, c = i & 63;
            sR4[r * 65 + c] = gR[i];
        }
        const float4* __restrict__ gD = (const float4*)(dDf + (size_t)b * 128 * 128);
        float4* sD4 = (float4*)sD;
        for (int i = t; i < 128 * 32; i += 256) {
            int r = i >> 5, c = i & 31;
            sD4[r * 33 + c] = gD[i];
        }
    }
    sy[t] = 0.0625f;   // 1/sqrt(256)
    __syncthreads();

    // --- power iteration for lambda_max ---
    for (int pi = 0; pi < NPOW; ++pi) {
        float g = matvec256(sR, sD, sy, t);
        float nr = blk_sum(g * g, red, t);
        sy[t] = g * (1.f / (sqrtf(nr) + 1e-12f));
        __syncthreads();
    }
    float s2;
    {
        float g = matvec256(sR, sD, sy, t);
        float lmax = blk_sum(sy[t] * g, red, t);
        s2 = 2.f / (2.f * lmax + 1e-12f);   // step * 2
    }

    // --- FISTA ---
    float w_loc[8];
#pragma unroll
    for (int j = 0; j < 8; ++j) w_loc[j] = 1.f / 256.f;
    float tk  = 1.f;
    float tau = 0.f;          // warm-started projection root
    sy[t] = 1.f / 256.f;
    __syncthreads();

#pragma unroll 1
    for (int it = 0; it < NITERS; ++it) {
        float g = matvec256(sR, sD, sy, t);
        sv[t] = sy[t] - s2 * g;             // v = y - step * (2 Q y)
        __syncthreads();

        // every warp loads full v (8 coords/lane, conflict-free)
        float v[8];
#pragma unroll
        for (int j = 0; j < 8; ++j) v[j] = sv[lane + 32 * j];

        // bracket via warp min/max (paired tree)
        float mn0 = fminf(fminf(v[0], v[1]), fminf(v[2], v[3]));
        float mn1 = fminf(fminf(v[4], v[5]), fminf(v[6], v[7]));
        float mx0 = fmaxf(fmaxf(v[0], v[1]), fmaxf(v[2], v[3]));
        float mx1 = fmaxf(fmaxf(v[4], v[5]), fmaxf(v[6], v[7]));
        float mn = fminf(mn0, mn1), mx = fmaxf(mx0, mx1);
#pragma unroll
        for (int o = 16; o > 0; o >>= 1) {
            mn = fminf(mn, __shfl_xor_sync(0xffffffffu, mn, o));
            mx = fmaxf(mx, __shfl_xor_sync(0xffffffffu, mx, o));
        }
        float lo = mn - CMAX, hi = mx + CMAX;
        if (!(tau > lo && tau < hi)) tau = 0.5f * (lo + hi);  // warm start clamp

        // safeguarded Newton with bitwise fixed-point early exit
#pragma unroll 1
        for (int nit = 0; nit < NEWTMAX; ++nit) {
            float s0 = 0.f, s1 = 0.f, c0 = 0.f, c1 = 0.f;
#pragma unroll
            for (int j = 0; j < 8; ++j) {
                float z  = v[j] - tau;
                float zc = fminf(fmaxf(z, -CMAX), CMAX);
                float ir = (fabsf(z) < CMAX) ? 1.f : 0.f;
                if (j & 1) { s1 += zc; c1 += ir; } else { s0 += zc; c0 += ir; }
            }
            float s = s0 + s1, cn = c0 + c1;
#pragma unroll
            for (int o = 16; o > 0; o >>= 1) {
                s  += __shfl_xor_sync(0xffffffffu, s,  o);
                cn += __shfl_xor_sync(0xffffffffu, cn, o);
            }
            if (s > 1.f) lo = tau; else hi = tau;
            float tn = (cn >= 1.f) ? tau + (s - 1.f) / cn : 0.5f * (lo + hi);
            if (!(tn > lo && tn < hi)) tn = 0.5f * (lo + hi);
            if (tn == tau) break;       // exact piece found -> Newton fixed point
            tau = tn;
        }

        // exact tau from the active set (reference's recompute formula)
        float sa = 0.f, sk = 0.f, si = 0.f;
#pragma unroll
        for (int j = 0; j < 8; ++j) {
            float z   = v[j] - tau;
            float inr = (fabsf(z) < CMAX) ? 1.f : 0.f;
            sa += inr * v[j];
            sk += ((z >= CMAX) ? 1.f : 0.f) - ((z <= -CMAX) ? 1.f : 0.f);
            si += inr;
        }
#pragma unroll
        for (int o = 16; o > 0; o >>= 1) {
            sa += __shfl_xor_sync(0xffffffffu, sa, o);
            sk += __shfl_xor_sync(0xffffffffu, sk, o);
            si += __shfl_xor_sync(0xffffffffu, si, o);
        }
        float tau2 = (sa + CMAX * sk - 1.f) / fmaxf(si, 1.f);

        // FISTA momentum (scalar, identical in all threads)
        float tn   = 0.5f * (1.f + sqrtf(1.f + 4.f * tk * tk));
        float coef = (tk - 1.f) / tn;
        tk = tn;

        float yn_own = 0.f;
#pragma unroll
        for (int j = 0; j < 8; ++j) {
            float wn = fminf(fmaxf(v[j] - tau2, -CMAX), CMAX);
            float yn = wn + coef * (wn - w_loc[j]);
            w_loc[j] = wn;
            if (j == wid) yn_own = yn;
        }
        sy[lane + 32 * wid] = yn_own;
        __syncthreads();
    }

    float w_own = w_loc[0];
#pragma unroll
    for (int j = 1; j < 8; ++j) if (j == wid) w_own = w_loc[j];
    out[(size_t)b * 256 + lane + 32 * wid] = w_own;
}

// ---------------------------------------------------------------------------
extern "C" void kernel_launch(void* const* d_in, const int* in_sizes, int n_in,
                              void* d_out, int out_size) {
    const float* A = (const float*)d_in[0];
    float* out = (float*)d_out;

    cudaFuncSetAttribute(fista_kernel,
                         cudaFuncAttributeMaxDynamicSharedMemorySize, SMEM_BYTES);

    qgemm_kernel<<<dim3(3, NB), 256>>>(A);
    fista_kernel<<<NB, 256, SMEM_BYTES>>>(out);
}

// round 5
// speedup vs baseline: 1.5033x; 1.5033x over previous
#include <cuda_runtime.h>
#include <cuda_bf16.h>
#include <math.h>

// ---------------------------------------------------------------------------
#define NB      512
#define NA      256
#define CMAX    0.05f
#define NITERS  300
#define NPOW    30
#define NEWT    14

__device__ float dRf[(size_t)NB * 128 * 256];   // rows 0..127 of Q, full width
__device__ float dDf[(size_t)NB * 128 * 128];   // Q[128+i][128+j]

// ---------------------------------------------------------------------------
// Kernel 1: Q = A^T A  (tiles (0,0),(0,1),(1,1); Q symmetric)
// ---------------------------------------------------------------------------
__global__ __launch_bounds__(256) void qgemm_kernel(const float* __restrict__ A) {
    const int tile = blockIdx.x;
    const int b    = blockIdx.y;
    const int cj   = (tile == 2) ? 128 : 0;
    const int ck   = (tile == 0) ? 0   : 128;

    __shared__ float sA[16][128];
    __shared__ float sB[16][128];

    const int tid = threadIdx.x;
    const int tx  = tid & 15;
    const int ty  = tid >> 4;

    float acc[8][8];
#pragma unroll
    for (int i = 0; i < 8; ++i)
#pragma unroll
        for (int j = 0; j < 8; ++j) acc[i][j] = 0.f;

    const float* __restrict__ Ab = A + (size_t)b * NA * NA;

    for (int ic = 0; ic < NA; ic += 16) {
#pragma unroll
        for (int u = 0; u < 2; ++u) {
            int idx = tid * 8 + u * 4;
            int r   = idx >> 7;
            int cc  = idx & 127;
            *(float4*)&sA[r][cc] = *(const float4*)&Ab[(size_t)(ic + r) * NA + cj + cc];
            *(float4*)&sB[r][cc] = *(const float4*)&Ab[(size_t)(ic + r) * NA + ck + cc];
        }
        __syncthreads();

#pragma unroll
        for (int kk = 0; kk < 16; ++kk) {
            float a8[8], b8[8];
            const float4* pa = (const float4*)&sA[kk][ty * 8];
            const float4* pb = (const float4*)&sB[kk][tx * 8];
            float4 a0 = pa[0], a1 = pa[1];
            float4 b0 = pb[0], b1 = pb[1];
            a8[0]=a0.x; a8[1]=a0.y; a8[2]=a0.z; a8[3]=a0.w;
            a8[4]=a1.x; a8[5]=a1.y; a8[6]=a1.z; a8[7]=a1.w;
            b8[0]=b0.x; b8[1]=b0.y; b8[2]=b0.z; b8[3]=b0.w;
            b8[4]=b1.x; b8[5]=b1.y; b8[6]=b1.z; b8[7]=b1.w;
#pragma unroll
            for (int i = 0; i < 8; ++i)
#pragma unroll
                for (int j = 0; j < 8; ++j)
                    acc[i][j] = fmaf(a8[i], b8[j], acc[i][j]);
        }
        __syncthreads();
    }

#pragma unroll
    for (int i = 0; i < 8; ++i) {
        int row = ty * 8 + i;
        float4 v0 = make_float4(acc[i][0], acc[i][1], acc[i][2], acc[i][3]);
        float4 v1 = make_float4(acc[i][4], acc[i][5], acc[i][6], acc[i][7]);
        if (tile < 2) {
            float* dst = dRf + ((size_t)b * 128 + row) * 256 + ck + tx * 8;
            *(float4*)dst       = v0;
            *(float4*)(dst + 4) = v1;
        } else {
            float* dst = dDf + ((size_t)b * 128 + row) * 128 + tx * 8;
            *(float4*)dst       = v0;
            *(float4*)(dst + 4) = v1;
        }
    }
}

// ---------------------------------------------------------------------------
// Kernel 2: per-batch FISTA. 512 threads, split-K matvec, warp projection.
// ---------------------------------------------------------------------------
#define TPB 512
#define RP 260
#define DP 132
#define SR_ELEMS (128 * RP)
#define SD_ELEMS (128 * DP)
#define SMEM_FLOATS (SR_ELEMS + SD_ELEMS + 256 + 512 + 32)
#define SMEM_BYTES (SMEM_FLOATS * 4)

// block reduction over 512 threads (power phase only)
__device__ __forceinline__ float blk_sum512(float a, float* red, int t) {
#pragma unroll
    for (int o = 16; o > 0; o >>= 1)
        a += __shfl_xor_sync(0xffffffffu, a, o);
    if ((t & 31) == 0) red[t >> 5] = a;
    __syncthreads();
    float r = 0.f;
#pragma unroll
    for (int i = 0; i < 16; ++i) r += red[i];
    __syncthreads();
    return r;
}

// half matvec: thread (u, h) sums 128 terms of g_u
__device__ __forceinline__ float matvec_half(const float* __restrict__ sR,
                                             const float* __restrict__ sD,
                                             const float* __restrict__ sy,
                                             int u, int h) {
    float g0 = 0.f, g1 = 0.f, g2 = 0.f, g3 = 0.f;
    const float4* __restrict__ y4 = (const float4*)sy;
    if (u < 128) {
        // row u of R, half h (contiguous float4)
        const float4* __restrict__ qr = (const float4*)(sR + u * RP) + h * 32;
        const float4* __restrict__ yy = y4 + h * 32;
#pragma unroll
        for (int k = 0; k < 32; ++k) {
            float4 q = qr[k], y = yy[k];
            g0 = fmaf(q.x, y.x, g0); g1 = fmaf(q.y, y.y, g1);
            g2 = fmaf(q.z, y.z, g2); g3 = fmaf(q.w, y.w, g3);
        }
    } else if (h == 0) {
        // column u of R (stride RP; lanes consecutive -> conflict-free)
        const float* __restrict__ qc = sR + u;
#pragma unroll
        for (int k4 = 0; k4 < 32; ++k4) {
            float4 y = y4[k4];
            const int k = k4 * 4;
            g0 = fmaf(qc[(k + 0) * RP], y.x, g0);
            g1 = fmaf(qc[(k + 1) * RP], y.y, g1);
            g2 = fmaf(qc[(k + 2) * RP], y.z, g2);
            g3 = fmaf(qc[(k + 3) * RP], y.w, g3);
        }
    } else {
        // row (u-128) of D (contiguous float4)
        const float4* __restrict__ dr = (const float4*)(sD + (u - 128) * DP);
#pragma unroll
        for (int k = 0; k < 32; ++k) {
            float4 q = dr[k], y = y4[k + 32];
            g0 = fmaf(q.x, y.x, g0); g1 = fmaf(q.y, y.y, g1);
            g2 = fmaf(q.z, y.z, g2); g3 = fmaf(q.w, y.w, g3);
        }
    }
    return (g0 + g1) + (g2 + g3);
}

__global__ __launch_bounds__(TPB) void fista_kernel(float* __restrict__ out) {
    extern __shared__ float sm[];
    float* sR  = sm;
    float* sD  = sm + SR_ELEMS;
    float* sy  = sD + SD_ELEMS;          // 256
    float* sp  = sy + 256;               // 512 partials
    float* red = sp + 512;               // 32

    const int b    = blockIdx.x;
    const int t    = threadIdx.x;
    const int lane = t & 31;
    const int wid  = t >> 5;             // 0..15
    const int u    = t & 255;
    const int h    = t >> 8;             // 0 or 1

    // --- load compressed Q into padded SMEM ---
    {
        const float4* __restrict__ gR = (const float4*)(dRf + (size_t)b * 128 * 256);
        float4* sR4 = (float4*)sR;
        for (int i = t; i < 128 * 64; i += TPB) {
            int r = i >> 6, c = i & 63;
            sR4[r * 65 + c] = gR[i];
        }
        const float4* __restrict__ gD = (const float4*)(dDf + (size_t)b * 128 * 128);
        float4* sD4 = (float4*)sD;
        for (int i = t; i < 128 * 32; i += TPB) {
            int r = i >> 5, c = i & 31;
            sD4[r * 33 + c] = gD[i];
        }
    }
    if (h == 0) sy[u] = 0.0625f;   // 1/sqrt(256)
    __syncthreads();

    // --- power iteration for lambda_max ---
    for (int pi = 0; pi < NPOW; ++pi) {
        sp[t] = matvec_half(sR, sD, sy, u, h);
        __syncthreads();
        float g = sp[u] + sp[u + 256];
        float nr = blk_sum512((h == 0) ? g * g : 0.f, red, t);
        if (h == 0) sy[u] = g * (1.f / (sqrtf(nr) + 1e-12f));
        __syncthreads();
    }
    float s2;
    {
        sp[t] = matvec_half(sR, sD, sy, u, h);
        __syncthreads();
        float g = sp[u] + sp[u + 256];
        float lmax = blk_sum512((h == 0) ? sy[u] * g : 0.f, red, t);
        s2 = 2.f / (2.f * lmax + 1e-12f);
    }

    // --- FISTA ---
    float w_loc[8], y_loc[8];
#pragma unroll
    for (int j = 0; j < 8; ++j) { w_loc[j] = 1.f / 256.f; y_loc[j] = 1.f / 256.f; }
    float tk = 1.f;
    if (h == 0) sy[u] = 1.f / 256.f;
    __syncthreads();

#pragma unroll 1
    for (int it = 0; it < NITERS; ++it) {
        sp[t] = matvec_half(sR, sD, sy, u, h);
        __syncthreads();

        if (wid < 8) {   // projection warps: each holds all 256 coords
            float v[8];
#pragma unroll
            for (int j = 0; j < 8; ++j) {
                int c = lane + 32 * j;
                float g = sp[c] + sp[c + 256];
                v[j] = y_loc[j] - s2 * g;
            }

            // bracket via warp min/max (paired tree)
            float mn0 = fminf(fminf(v[0], v[1]), fminf(v[2], v[3]));
            float mn1 = fminf(fminf(v[4], v[5]), fminf(v[6], v[7]));
            float mx0 = fmaxf(fmaxf(v[0], v[1]), fmaxf(v[2], v[3]));
            float mx1 = fmaxf(fmaxf(v[4], v[5]), fmaxf(v[6], v[7]));
            float mn = fminf(mn0, mn1), mx = fmaxf(mx0, mx1);
#pragma unroll
            for (int o = 16; o > 0; o >>= 1) {
                mn = fminf(mn, __shfl_xor_sync(0xffffffffu, mn, o));
                mx = fmaxf(mx, __shfl_xor_sync(0xffffffffu, mx, o));
            }
            float lo = mn - CMAX, hi = mx + CMAX;
            float tau = 0.5f * (lo + hi);

            // fixed-count safeguarded Newton
#pragma unroll 1
            for (int nit = 0; nit < NEWT; ++nit) {
                float s0 = 0.f, s1 = 0.f, c0 = 0.f, c1 = 0.f;
#pragma unroll
                for (int j = 0; j < 8; ++j) {
                    float z  = v[j] - tau;
                    float zc = fminf(fmaxf(z, -CMAX), CMAX);
                    float ir = (fabsf(z) < CMAX) ? 1.f : 0.f;
                    if (j & 1) { s1 += zc; c1 += ir; } else { s0 += zc; c0 += ir; }
                }
                float s = s0 + s1, cn = c0 + c1;
#pragma unroll
                for (int o = 16; o > 0; o >>= 1) {
                    s  += __shfl_xor_sync(0xffffffffu, s,  o);
                    cn += __shfl_xor_sync(0xffffffffu, cn, o);
                }
                if (s > 1.f) lo = tau; else hi = tau;
                float tn = (cn >= 1.f) ? tau + __fdividef(s - 1.f, cn)
                                       : 0.5f * (lo + hi);
                if (!(tn > lo && tn < hi)) tn = 0.5f * (lo + hi);
                tau = tn;
            }

            // exact tau from the active set (reference's recompute)
            float sa = 0.f, sk = 0.f, si = 0.f;
#pragma unroll
            for (int j = 0; j < 8; ++j) {
                float z   = v[j] - tau;
                float inr = (fabsf(z) < CMAX) ? 1.f : 0.f;
                sa += inr * v[j];
                sk += ((z >= CMAX) ? 1.f : 0.f) - ((z <= -CMAX) ? 1.f : 0.f);
                si += inr;
            }
#pragma unroll
            for (int o = 16; o > 0; o >>= 1) {
                sa += __shfl_xor_sync(0xffffffffu, sa, o);
                sk += __shfl_xor_sync(0xffffffffu, sk, o);
                si += __shfl_xor_sync(0xffffffffu, si, o);
            }
            float tau2 = (sa + CMAX * sk - 1.f) / fmaxf(si, 1.f);

            // FISTA momentum
            float tn   = 0.5f * (1.f + sqrtf(1.f + 4.f * tk * tk));
            float coef = (tk - 1.f) / tn;
            tk = tn;

            float yn_own = 0.f;
#pragma unroll
            for (int j = 0; j < 8; ++j) {
                float wn = fminf(fmaxf(v[j] - tau2, -CMAX), CMAX);
                float yn = wn + coef * (wn - w_loc[j]);
                w_loc[j] = wn;
                y_loc[j] = yn;
                if (j == wid) yn_own = yn;
            }
            sy[lane + 32 * wid] = yn_own;   // disjoint owner writes
        }
        __syncthreads();
    }

    if (wid < 8) {
        float w_own = w_loc[0];
#pragma unroll
        for (int j = 1; j < 8; ++j) if (j == wid) w_own = w_loc[j];
        out[(size_t)b * 256 + lane + 32 * wid] = w_own;
    }
}

// ---------------------------------------------------------------------------
extern "C" void kernel_launch(void* const* d_in, const int* in_sizes, int n_in,
                              void* d_out, int out_size) {
    const float* A = (const float*)d_in[0];
    float* out = (float*)d_out;

    cudaFuncSetAttribute(fista_kernel,
                         cudaFuncAttributeMaxDynamicSharedMemorySize, SMEM_BYTES);

    qgemm_kernel<<<dim3(3, NB), 256>>>(A);
    fista_kernel<<<NB, TPB, SMEM_BYTES>>>(out);
}